// round 10
// baseline (speedup 1.0000x reference)
#include <cuda_runtime.h>
#include <math.h>
#include <stdint.h>

#define B_  16
#define D_  96
#define T_  512
#define H_  1024
#define BD_ (B_*D_)

// ---- scratch ----
__device__ float g_A[B_*D_*D_];    // softmax corr, tf32-rounded
__device__ float g_x1[BD_*T_];     // attn+res (for BN stats)
__device__ float g_x2r[BD_*T_];    // BN(x1) tf32-rounded (GEMM1 A + GEMM2 residual)
__device__ float g_h[BD_*H_];      // GELU output, tf32-rounded
__device__ float g_y[2*BD_*T_];    // GEMM2 split-K partials
__device__ float g_w1t[H_*T_];     // W1^T [H][T], tf32-rounded
__device__ float g_w2t[T_*H_];     // W2^T [T][H], tf32-rounded

extern __shared__ char dyn_smem[];

__device__ __forceinline__ float warp_sum(float v){
    #pragma unroll
    for(int o=16;o>0;o>>=1) v += __shfl_xor_sync(0xffffffffu, v, o);
    return v;
}
__device__ __forceinline__ float warp_max(float v){
    #pragma unroll
    for(int o=16;o>0;o>>=1) v = fmaxf(v, __shfl_xor_sync(0xffffffffu, v, o));
    return v;
}
__device__ __forceinline__ float to_tf32f(float x){
    uint32_t u; asm("cvt.rna.tf32.f32 %0, %1;" : "=r"(u) : "f"(x));
    return __uint_as_float(u);
}
__device__ __forceinline__ uint32_t smem_u32(const void* p){
    uint32_t a;
    asm("{ .reg .u64 t; cvta.to.shared.u64 t, %1; cvt.u32.u64 %0, t; }" : "=r"(a) : "l"(p));
    return a;
}
__device__ __forceinline__ void mma_tf32(float4& d, const uint32_t a[4], uint32_t b0, uint32_t b1){
    asm volatile("mma.sync.aligned.m16n8k8.row.col.f32.tf32.tf32.f32 "
        "{%0,%1,%2,%3}, {%4,%5,%6,%7}, {%8,%9}, {%0,%1,%2,%3};"
        : "+f"(d.x), "+f"(d.y), "+f"(d.z), "+f"(d.w)
        : "r"(a[0]), "r"(a[1]), "r"(a[2]), "r"(a[3]), "r"(b0), "r"(b1));
}
__device__ __forceinline__ void ldsm_x4(uint32_t* r, uint32_t addr){
    asm volatile("ldmatrix.sync.aligned.m8n8.x4.shared.b16 {%0,%1,%2,%3}, [%4];"
        : "=r"(r[0]), "=r"(r[1]), "=r"(r[2]), "=r"(r[3]) : "r"(addr));
}
__device__ __forceinline__ void cp16(uint32_t dst, const void* src){
    asm volatile("cp.async.ca.shared.global [%0], [%1], 16;" :: "r"(dst), "l"(src));
}
#define CP_COMMIT() asm volatile("cp.async.commit_group;" ::: "memory")
#define CP_WAIT1()  asm volatile("cp.async.wait_group 1;" ::: "memory")
#define CP_WAIT0()  asm volatile("cp.async.wait_group 0;" ::: "memory")

// K0: merged weight transposes + corr softmax. grid 1040 x 256 thr.
__global__ void k_pre(const float* __restrict__ W1, float* __restrict__ W1t,
                      const float* __restrict__ W2, float* __restrict__ W2t,
                      const float* __restrict__ res){
    __shared__ float tile[32][33];
    __shared__ float s[D_];
    int bid = blockIdx.x;
    if (bid < 1024){
        const float* W; float* Wt; int R, C, bx, by;
        if (bid < 512){ W = W1; Wt = W1t; R = T_; C = H_;
            bx = (bid & 31)*32; by = (bid >> 5)*32; }
        else { int idx = bid - 512; W = W2; Wt = W2t; R = H_; C = T_;
            bx = (idx & 15)*32; by = (idx >> 4)*32; }
        int tx = threadIdx.x & 31, ty = threadIdx.x >> 5;
        #pragma unroll
        for (int r = 0; r < 4; r++)
            tile[ty + r*8][tx] = to_tf32f(W[(size_t)(by + ty + r*8)*C + bx + tx]);
        __syncthreads();
        #pragma unroll
        for (int r = 0; r < 4; r++)
            Wt[(size_t)(bx + ty + r*8)*R + by + tx] = tile[tx][ty + r*8];
        return;
    }
    int b = bid - 1024;
    int w = threadIdx.x >> 5, lane = threadIdx.x & 31;
    for (int r = w; r < D_; r += 8){
        const float4* p = (const float4*)(res + (b*D_ + r)*T_);
        float v = 0.f;
        #pragma unroll
        for (int k = 0; k < 4; k++){
            float4 q = p[lane + k*32];
            v += (q.x + q.y) + (q.z + q.w);
        }
        v = warp_sum(v);
        if (lane == 0) s[r] = v;
    }
    __syncthreads();
    const float SCALE = 1.0f/11585.237502960395f;   // 1/512^1.5
    for (int r = w; r < D_; r += 8){
        float si = s[r];
        float z0 = si * s[lane     ] * SCALE;
        float z1 = si * s[lane + 32] * SCALE;
        float z2 = si * s[lane + 64] * SCALE;
        float m = warp_max(fmaxf(z0, fmaxf(z1, z2)));
        float e0 = expf(z0 - m), e1 = expf(z1 - m), e2 = expf(z2 - m);
        float inv = 1.f / warp_sum(e0 + e1 + e2);
        float* o = g_A + (b*D_ + r)*D_;
        o[lane]      = to_tf32f(e0 * inv);
        o[lane + 32] = to_tf32f(e1 * inv);
        o[lane + 64] = to_tf32f(e2 * inv);
    }
}

// K2: x1 = (I+A) @ X via tf32 mma. grid (T/64, B), 256 thr.
#define AT_SB_OFF (128*100)
#define ATTN_SMEM ((128*100 + 64*100)*4)   // 76800 B
__global__ void __launch_bounds__(256) k_attn(const float* __restrict__ res){
    float* sm = (float*)dyn_smem;
    float* sA = sm;
    float* sB = sm + AT_SB_OFF;
    uint32_t sbase = smem_u32(sm);
    int b  = blockIdx.y;
    int t0 = blockIdx.x * 64;
    int tid = threadIdx.x, lane = tid & 31, w = tid >> 5;

    for (int i = tid; i < D_*D_/4; i += 256){
        int d = (i*4)/D_, e = (i*4)%D_;
        *(float4*)&sA[d*100 + e] = *(const float4*)&g_A[(b*D_+d)*D_ + e];
    }
    for (int i = tid; i < D_*64; i += 256){
        int e = i >> 6, n = i & 63;
        sB[n*100 + e] = to_tf32f(res[(b*D_+e)*T_ + t0 + n]);
    }
    __syncthreads();

    int wm = (w & 3) * 32, wn = (w >> 2) * 32;
    uint32_t aF0, aF1, bF0, bF1;
    {
        int rlo = lane & 7, rmid = (lane >> 3) & 1, khi = lane >> 4;
        aF0 = sbase + (uint32_t)((wm + rlo + 8*rmid)*400 + 16*khi);
        aF1 = aF0 + 16*400;
        bF0 = sbase + (uint32_t)(AT_SB_OFF*4 + (wn      + khi*8 + rlo)*400 + 16*rmid);
        bF1 = sbase + (uint32_t)(AT_SB_OFF*4 + (wn + 16 + khi*8 + rlo)*400 + 16*rmid);
    }
    float4 acc[2][4];
    #pragma unroll
    for (int i = 0; i < 2; i++)
        #pragma unroll
        for (int j = 0; j < 4; j++) acc[i][j] = make_float4(0.f,0.f,0.f,0.f);

    #pragma unroll
    for (int ks = 0; ks < 12; ks++){
        uint32_t a0[4], a1[4], b0[4], b1[4];
        ldsm_x4(a0, aF0 + ks*32);
        ldsm_x4(a1, aF1 + ks*32);
        ldsm_x4(b0, bF0 + ks*32);
        ldsm_x4(b1, bF1 + ks*32);
        mma_tf32(acc[0][0], a0, b0[0], b0[1]);
        mma_tf32(acc[0][1], a0, b0[2], b0[3]);
        mma_tf32(acc[0][2], a0, b1[0], b1[1]);
        mma_tf32(acc[0][3], a0, b1[2], b1[3]);
        mma_tf32(acc[1][0], a1, b0[0], b0[1]);
        mma_tf32(acc[1][1], a1, b0[2], b0[3]);
        mma_tf32(acc[1][2], a1, b1[0], b1[1]);
        mma_tf32(acc[1][3], a1, b1[2], b1[3]);
    }

    if (wm < 96){
        int tr = lane >> 2, tc = lane & 3;
        #pragma unroll
        for (int i = 0; i < 2; i++){
            int r0 = wm + i*16 + tr;
            int r1 = r0 + 8;
            #pragma unroll
            for (int j = 0; j < 4; j++){
                int cl = wn + j*8 + tc*2;
                float4 v = acc[i][j];
                v.x += sB[cl*100 + r0];  v.y += sB[(cl+1)*100 + r0];
                v.z += sB[cl*100 + r1];  v.w += sB[(cl+1)*100 + r1];
                *(float2*)&g_x1[(b*D_+r0)*T_ + t0 + cl] = make_float2(v.x, v.y);
                *(float2*)&g_x1[(b*D_+r1)*T_ + t0 + cl] = make_float2(v.z, v.w);
            }
        }
    }
}

// K3: fused BN stats + apply, single read. grid=D_, 512 thr.
__global__ void k_bn(const float* __restrict__ gamma, const float* __restrict__ beta){
    int d = blockIdx.x;
    int tid = threadIdx.x;
    float4 v[4];
    float s = 0.f, ss = 0.f;
    #pragma unroll
    for (int r = 0; r < 4; r++){
        int i = tid + r*512;
        int b = i >> 7, t4 = i & 127;
        v[r] = *(const float4*)&g_x1[(b*D_+d)*T_ + t4*4];
        s  += (v[r].x + v[r].y) + (v[r].z + v[r].w);
        ss += (v[r].x*v[r].x + v[r].y*v[r].y) + (v[r].z*v[r].z + v[r].w*v[r].w);
    }
    s = warp_sum(s); ss = warp_sum(ss);
    __shared__ float r1[16], r2[16];
    __shared__ float bsc, bof;
    int w = tid >> 5;
    if ((tid & 31) == 0){ r1[w] = s; r2[w] = ss; }
    __syncthreads();
    if (tid == 0){
        float S = 0.f, SS = 0.f;
        #pragma unroll
        for (int k = 0; k < 16; k++){ S += r1[k]; SS += r2[k]; }
        const float invN = 1.f/(float)(B_*T_);
        float mean = S * invN;
        float var  = SS * invN - mean*mean;
        float rs = rsqrtf(var + 1e-5f);
        float sc = rs * gamma[d];
        bsc = sc; bof = beta[d] - mean * sc;
    }
    __syncthreads();
    float sc = bsc, of = bof;
    #pragma unroll
    for (int r = 0; r < 4; r++){
        int i = tid + r*512;
        int b = i >> 7, t4 = i & 127;
        float4 q = v[r];
        q.x = to_tf32f(fmaf(q.x, sc, of));
        q.y = to_tf32f(fmaf(q.y, sc, of));
        q.z = to_tf32f(fmaf(q.z, sc, of));
        q.w = to_tf32f(fmaf(q.w, sc, of));
        *(float4*)&g_x2r[(b*D_+d)*T_ + t4*4] = q;
    }
}

// ======================= tf32 mma.sync GEMM (ldmatrix + cp.async) =======================
// CTA 128x64, BK=32, 8 warps (4m x 2n), warp tile 32x32, 3-stage cp.async, 2 CTA/SM.
// SPLITK: blockIdx.z picks K-half; partial z writes to C + z*M*N; bias/res only in z==0.
#define ASTG 18432   // 128*36*4
#define BSTG 9216    // 64*36*4
#define STG  (ASTG + BSTG)
#define GEMM_SMEM (3*STG)   // 82944

template<bool GELU, bool ROUND, bool RESID, bool SPLITK>
__global__ void __launch_bounds__(256, 2) k_mma(
    const float* __restrict__ A, const float* __restrict__ Bt,
    const float* __restrict__ bias, const float* __restrict__ Res,
    float* __restrict__ C, int M, int N, int K)
{
    uint32_t sbase = smem_u32(dyn_smem);
    int tid = threadIdx.x, lane = tid & 31, w = tid >> 5;
    int wm = (w & 3) * 32, wn = (w >> 2) * 32;
    int bn = blockIdx.x * 64, bm = blockIdx.y * 128;
    int kz = SPLITK ? blockIdx.z : 0;
    int koff = SPLITK ? kz * (K >> 1) : 0;
    const int KT = (SPLITK ? (K >> 1) : K) / 32;
    bool lead = (!SPLITK) || (kz == 0);

    uint32_t aSm[4]; const float* aG[4];
    #pragma unroll
    for (int r = 0; r < 4; r++){
        int idx = tid + r*256, m = idx >> 3, kc = idx & 7;
        aSm[r] = (uint32_t)(m*144 + kc*16);
        aG[r]  = A + (size_t)(bm + m)*K + koff + kc*4;
    }
    uint32_t bSm[2]; const float* bG[2];
    #pragma unroll
    for (int r = 0; r < 2; r++){
        int idx = tid + r*256, n = idx >> 3, kc = idx & 7;
        bSm[r] = (uint32_t)(ASTG + n*144 + kc*16);
        bG[r]  = Bt + (size_t)(bn + n)*K + koff + kc*4;
    }

    uint32_t aF[2], bF[2];
    {
        int rlo = lane & 7, rmid = (lane >> 3) & 1, khi = lane >> 4;
        aF[0] = (uint32_t)((wm + rlo + 8*rmid)*144 + 16*khi);
        aF[1] = aF[0] + 16*144;
        bF[0] = (uint32_t)(ASTG + (wn      + khi*8 + rlo)*144 + 16*rmid);
        bF[1] = (uint32_t)(ASTG + (wn + 16 + khi*8 + rlo)*144 + 16*rmid);
    }

    float4 acc[2][4];
    #pragma unroll
    for (int i = 0; i < 2; i++)
        #pragma unroll
        for (int j = 0; j < 4; j++) acc[i][j] = make_float4(0.f,0.f,0.f,0.f);

    #pragma unroll
    for (int s = 0; s < 2; s++){
        uint32_t st = sbase + s*STG;
        #pragma unroll
        for (int r = 0; r < 4; r++) cp16(st + aSm[r], aG[r] + s*32);
        #pragma unroll
        for (int r = 0; r < 2; r++) cp16(st + bSm[r], bG[r] + s*32);
        CP_COMMIT();
    }

    int cur = 0, nxtbuf = 2;
    for (int kt = 0; kt < KT; kt++){
        if (kt < KT-1) CP_WAIT1(); else CP_WAIT0();
        __syncthreads();
        if (kt + 2 < KT){
            uint32_t st = sbase + nxtbuf*STG;
            #pragma unroll
            for (int r = 0; r < 4; r++) cp16(st + aSm[r], aG[r] + (kt+2)*32);
            #pragma unroll
            for (int r = 0; r < 2; r++) cp16(st + bSm[r], bG[r] + (kt+2)*32);
            CP_COMMIT();
        }
        uint32_t st = sbase + cur*STG;
        #pragma unroll
        for (int ks = 0; ks < 4; ks++){
            uint32_t a0[4], a1[4], b0[4], b1[4];
            ldsm_x4(a0, st + aF[0] + ks*32);
            ldsm_x4(a1, st + aF[1] + ks*32);
            ldsm_x4(b0, st + bF[0] + ks*32);
            ldsm_x4(b1, st + bF[1] + ks*32);
            mma_tf32(acc[0][0], a0, b0[0], b0[1]);
            mma_tf32(acc[0][1], a0, b0[2], b0[3]);
            mma_tf32(acc[0][2], a0, b1[0], b1[1]);
            mma_tf32(acc[0][3], a0, b1[2], b1[3]);
            mma_tf32(acc[1][0], a1, b0[0], b0[1]);
            mma_tf32(acc[1][1], a1, b0[2], b0[3]);
            mma_tf32(acc[1][2], a1, b1[0], b1[1]);
            mma_tf32(acc[1][3], a1, b1[2], b1[3]);
        }
        cur = (cur + 1 == 3) ? 0 : cur + 1;
        nxtbuf = (nxtbuf + 1 == 3) ? 0 : nxtbuf + 1;
    }

    float* Cz = C + (SPLITK ? (size_t)kz * M * N : 0);
    int tr = lane >> 2, tc = lane & 3;
    #pragma unroll
    for (int i = 0; i < 2; i++){
        int r0 = bm + wm + i*16 + tr;
        int r1 = r0 + 8;
        #pragma unroll
        for (int j = 0; j < 4; j++){
            int col = bn + wn + j*8 + tc*2;
            float4 v = acc[i][j];
            if (lead){
                float2 bb = *(const float2*)&bias[col];
                v.x += bb.x; v.y += bb.y; v.z += bb.x; v.w += bb.y;
            }
            if (GELU){
                v.x = 0.5f*v.x*(1.0f + erff(v.x*0.7071067811865476f));
                v.y = 0.5f*v.y*(1.0f + erff(v.y*0.7071067811865476f));
                v.z = 0.5f*v.z*(1.0f + erff(v.z*0.7071067811865476f));
                v.w = 0.5f*v.w*(1.0f + erff(v.w*0.7071067811865476f));
            }
            if (RESID && lead){
                float2 q0 = *(const float2*)&Res[(size_t)r0*N + col];
                float2 q1 = *(const float2*)&Res[(size_t)r1*N + col];
                v.x += q0.x; v.y += q0.y; v.z += q1.x; v.w += q1.y;
            }
            if (ROUND){
                v.x = to_tf32f(v.x); v.y = to_tf32f(v.y);
                v.z = to_tf32f(v.z); v.w = to_tf32f(v.w);
            }
            *(float2*)&Cz[(size_t)r0*N + col] = make_float2(v.x, v.y);
            *(float2*)&Cz[(size_t)r1*N + col] = make_float2(v.z, v.w);
        }
    }
}

// K6: LayerNorm over T (sums the 2 split-K partials), write final output
__global__ void k_ln(const float* __restrict__ lng, const float* __restrict__ lnb,
                     float* __restrict__ out){
    int row = blockIdx.x;
    const float* y0 = g_y + (size_t)row*T_;
    const float* y1 = g_y + (size_t)BD_*T_ + (size_t)row*T_;
    int tid = threadIdx.x;
    float a = y0[tid]       + y1[tid];
    float b = y0[tid + 256] + y1[tid + 256];
    __shared__ float red[8];
    int w = tid >> 5;
    float s = warp_sum(a + b);
    if ((tid & 31) == 0) red[w] = s;
    __syncthreads();
    float S = 0.f;
    #pragma unroll
    for (int k = 0; k < 8; k++) S += red[k];
    float mean = S * (1.f/512.f);
    float d0 = a - mean, d1 = b - mean;
    __syncthreads();
    float ss = warp_sum(d0*d0 + d1*d1);
    if ((tid & 31) == 0) red[w] = ss;
    __syncthreads();
    float SS = 0.f;
    #pragma unroll
    for (int k = 0; k < 8; k++) SS += red[k];
    float rs = rsqrtf(SS * (1.f/512.f) + 1e-5f);
    out[row*T_ + tid]       = d0*rs*lng[tid]       + lnb[tid];
    out[row*T_ + tid + 256] = d1*rs*lng[tid + 256] + lnb[tid + 256];
}

extern "C" void kernel_launch(void* const* d_in, const int* in_sizes, int n_in,
                              void* d_out, int out_size){
    const float* residual = (const float*)d_in[0];
    const float* bn_g = (const float*)d_in[1];
    const float* bn_b = (const float*)d_in[2];
    const float* ln_g = (const float*)d_in[3];
    const float* ln_b = (const float*)d_in[4];
    const float* W1   = (const float*)d_in[5];
    const float* b1   = (const float*)d_in[6];
    const float* W2   = (const float*)d_in[7];
    const float* b2   = (const float*)d_in[8];
    float* out = (float*)d_out;

    cudaFuncSetAttribute(k_attn, cudaFuncAttributeMaxDynamicSharedMemorySize, ATTN_SMEM);
    cudaFuncSetAttribute(k_mma<true,  true,  false, false>, cudaFuncAttributeMaxDynamicSharedMemorySize, GEMM_SMEM);
    cudaFuncSetAttribute(k_mma<false, false, true,  true >, cudaFuncAttributeMaxDynamicSharedMemorySize, GEMM_SMEM);

    float *px2r, *ph, *py, *pw1t, *pw2t;
    cudaGetSymbolAddress((void**)&px2r, g_x2r);
    cudaGetSymbolAddress((void**)&ph,   g_h);
    cudaGetSymbolAddress((void**)&py,   g_y);
    cudaGetSymbolAddress((void**)&pw1t, g_w1t);
    cudaGetSymbolAddress((void**)&pw2t, g_w2t);

    k_pre<<<1024 + B_, 256>>>(W1, pw1t, W2, pw2t, residual);

    dim3 ga(T_/64, B_);
    k_attn<<<ga, 256, ATTN_SMEM>>>(residual);
    k_bn<<<D_, 512>>>(bn_g, bn_b);

    // GEMM1: h = tf32( GELU(x2r @ W1 + b1) )   [1536 x 1024 x 512], 128x64 tiles, 192 CTAs
    dim3 g1(H_/64, BD_/128);
    k_mma<true,  true,  false, false><<<g1, 256, GEMM_SMEM>>>(px2r, pw1t, b1, nullptr, ph, BD_, H_, T_);
    // GEMM2: y = h @ W2 + b2 + x2r, split-K x2  [1536 x 512 x 1024], 192 CTAs
    dim3 g2(T_/64, BD_/128, 2);
    k_mma<false, false, true,  true ><<<g2, 256, GEMM_SMEM>>>(ph, pw2t, b2, px2r, py, BD_, T_, H_);

    k_ln<<<BD_, 256>>>(ln_g, ln_b, out);
}

// round 11
// speedup vs baseline: 1.3637x; 1.3637x over previous
#include <cuda_runtime.h>
#include <cuda_fp16.h>
#include <math.h>
#include <stdint.h>

#define B_  16
#define D_  96
#define T_  512
#define H_  1024
#define BD_ (B_*D_)

// ---- scratch ----
__device__ float  g_A[B_*D_*D_];    // softmax corr (fp32; converted to half at attn staging)
__device__ float  g_x1[BD_*T_];     // attn+res (fp32, for BN stats)
__device__ __half g_x2r[BD_*T_];    // BN(x1) in fp16 (GEMM1 A + GEMM2 residual)
__device__ __half g_h[BD_*H_];      // GELU output fp16
__device__ float  g_y[2*BD_*T_];    // GEMM2 split-K partials (fp32)
__device__ __half g_w1t[H_*T_];     // W1^T [H][T] fp16
__device__ __half g_w2t[T_*H_];     // W2^T [T][H] fp16

extern __shared__ char dyn_smem[];

__device__ __forceinline__ float warp_sum(float v){
    #pragma unroll
    for(int o=16;o>0;o>>=1) v += __shfl_xor_sync(0xffffffffu, v, o);
    return v;
}
__device__ __forceinline__ float warp_max(float v){
    #pragma unroll
    for(int o=16;o>0;o>>=1) v = fmaxf(v, __shfl_xor_sync(0xffffffffu, v, o));
    return v;
}
__device__ __forceinline__ uint32_t smem_u32(const void* p){
    uint32_t a;
    asm("{ .reg .u64 t; cvta.to.shared.u64 t, %1; cvt.u32.u64 %0, t; }" : "=r"(a) : "l"(p));
    return a;
}
// fp16 mma: D(f32) += A(f16 m16k16) * B(f16 k16n8)
__device__ __forceinline__ void mma_f16(float4& d, const uint32_t a[4], uint32_t b0, uint32_t b1){
    asm volatile("mma.sync.aligned.m16n8k16.row.col.f32.f16.f16.f32 "
        "{%0,%1,%2,%3}, {%4,%5,%6,%7}, {%8,%9}, {%0,%1,%2,%3};"
        : "+f"(d.x), "+f"(d.y), "+f"(d.z), "+f"(d.w)
        : "r"(a[0]), "r"(a[1]), "r"(a[2]), "r"(a[3]), "r"(b0), "r"(b1));
}
__device__ __forceinline__ void ldsm_x4(uint32_t* r, uint32_t addr){
    asm volatile("ldmatrix.sync.aligned.m8n8.x4.shared.b16 {%0,%1,%2,%3}, [%4];"
        : "=r"(r[0]), "=r"(r[1]), "=r"(r[2]), "=r"(r[3]) : "r"(addr));
}
__device__ __forceinline__ void cp16(uint32_t dst, const void* src){
    asm volatile("cp.async.ca.shared.global [%0], [%1], 16;" :: "r"(dst), "l"(src));
}
#define CP_COMMIT() asm volatile("cp.async.commit_group;" ::: "memory")
#define CP_WAIT1()  asm volatile("cp.async.wait_group 1;" ::: "memory")
#define CP_WAIT0()  asm volatile("cp.async.wait_group 0;" ::: "memory")

// K0: merged weight transposes (fp32 -> fp16 transposed) + corr softmax. grid 1040 x 256.
__global__ void k_pre(const float* __restrict__ W1, __half* __restrict__ W1t,
                      const float* __restrict__ W2, __half* __restrict__ W2t,
                      const float* __restrict__ res){
    __shared__ float tile[32][33];
    __shared__ float s[D_];
    int bid = blockIdx.x;
    if (bid < 1024){
        const float* W; __half* Wt; int R, C, bx, by;
        if (bid < 512){ W = W1; Wt = W1t; R = T_; C = H_;
            bx = (bid & 31)*32; by = (bid >> 5)*32; }
        else { int idx = bid - 512; W = W2; Wt = W2t; R = H_; C = T_;
            bx = (idx & 15)*32; by = (idx >> 4)*32; }
        int tx = threadIdx.x & 31, ty = threadIdx.x >> 5;
        #pragma unroll
        for (int r = 0; r < 4; r++)
            tile[ty + r*8][tx] = W[(size_t)(by + ty + r*8)*C + bx + tx];
        __syncthreads();
        #pragma unroll
        for (int r = 0; r < 4; r++)
            Wt[(size_t)(bx + ty + r*8)*R + by + tx] = __float2half_rn(tile[tx][ty + r*8]);
        return;
    }
    int b = bid - 1024;
    int w = threadIdx.x >> 5, lane = threadIdx.x & 31;
    for (int r = w; r < D_; r += 8){
        const float4* p = (const float4*)(res + (b*D_ + r)*T_);
        float v = 0.f;
        #pragma unroll
        for (int k = 0; k < 4; k++){
            float4 q = p[lane + k*32];
            v += (q.x + q.y) + (q.z + q.w);
        }
        v = warp_sum(v);
        if (lane == 0) s[r] = v;
    }
    __syncthreads();
    const float SCALE = 1.0f/11585.237502960395f;   // 1/512^1.5
    for (int r = w; r < D_; r += 8){
        float si = s[r];
        float z0 = si * s[lane     ] * SCALE;
        float z1 = si * s[lane + 32] * SCALE;
        float z2 = si * s[lane + 64] * SCALE;
        float m = warp_max(fmaxf(z0, fmaxf(z1, z2)));
        float e0 = expf(z0 - m), e1 = expf(z1 - m), e2 = expf(z2 - m);
        float inv = 1.f / warp_sum(e0 + e1 + e2);
        float* o = g_A + (b*D_ + r)*D_;
        o[lane]      = e0 * inv;
        o[lane + 32] = e1 * inv;
        o[lane + 64] = e2 * inv;
    }
}

// K2: x1 = (I+A) @ X via fp16 mma. grid (T/64, B), 256 thr.
// sA [128 m][104 h] (rows 96-127 garbage, results discarded), sB [64 t][104 h].
#define AT_SB_OFF (128*104)            // halves
#define ATTN_SMEM ((128*104 + 64*104)*2)   // 39936 B
__global__ void __launch_bounds__(256) k_attn(const float* __restrict__ res){
    __half* sm = (__half*)dyn_smem;
    __half* sA = sm;
    __half* sB = sm + AT_SB_OFF;
    uint32_t sbase = smem_u32(sm);
    int b  = blockIdx.y;
    int t0 = blockIdx.x * 64;
    int tid = threadIdx.x, lane = tid & 31, w = tid >> 5;

    // stage A [96x96] -> half
    for (int i = tid; i < D_*D_/4; i += 256){
        int d = (i*4)/D_, e = (i*4)%D_;
        float4 v = *(const float4*)&g_A[(b*D_+d)*D_ + e];
        __half2 h01 = __floats2half2_rn(v.x, v.y);
        __half2 h23 = __floats2half2_rn(v.z, v.w);
        *(__half2*)&sA[d*104 + e]     = h01;
        *(__half2*)&sA[d*104 + e + 2] = h23;
    }
    // stage X^T: sB[n][e] = half(res[b,e,t0+n])
    for (int i = tid; i < D_*64; i += 256){
        int e = i >> 6, n = i & 63;
        sB[n*104 + e] = __float2half_rn(res[(b*D_+e)*T_ + t0 + n]);
    }
    __syncthreads();

    int wm = (w & 3) * 32, wn = (w >> 2) * 32;
    uint32_t aF0, aF1, bF0, bF1;
    {
        int rlo = lane & 7, rmid = (lane >> 3) & 1, khi = lane >> 4;
        aF0 = sbase + (uint32_t)((wm + rlo + 8*rmid)*208 + 16*khi);
        aF1 = aF0 + 16*208;
        bF0 = sbase + (uint32_t)(AT_SB_OFF*2 + (wn      + khi*8 + rlo)*208 + 16*rmid);
        bF1 = sbase + (uint32_t)(AT_SB_OFF*2 + (wn + 16 + khi*8 + rlo)*208 + 16*rmid);
    }
    float4 acc[2][4];
    #pragma unroll
    for (int i = 0; i < 2; i++)
        #pragma unroll
        for (int j = 0; j < 4; j++) acc[i][j] = make_float4(0.f,0.f,0.f,0.f);

    #pragma unroll
    for (int ks = 0; ks < 6; ks++){            // 6 x k16 = 96
        uint32_t a0[4], a1[4], b0[4], b1[4];
        ldsm_x4(a0, aF0 + ks*32);
        ldsm_x4(a1, aF1 + ks*32);
        ldsm_x4(b0, bF0 + ks*32);
        ldsm_x4(b1, bF1 + ks*32);
        mma_f16(acc[0][0], a0, b0[0], b0[1]);
        mma_f16(acc[0][1], a0, b0[2], b0[3]);
        mma_f16(acc[0][2], a0, b1[0], b1[1]);
        mma_f16(acc[0][3], a0, b1[2], b1[3]);
        mma_f16(acc[1][0], a1, b0[0], b0[1]);
        mma_f16(acc[1][1], a1, b0[2], b0[3]);
        mma_f16(acc[1][2], a1, b1[0], b1[1]);
        mma_f16(acc[1][3], a1, b1[2], b1[3]);
    }

    if (wm < 96){
        int tr = lane >> 2, tc = lane & 3;
        #pragma unroll
        for (int i = 0; i < 2; i++){
            int r0 = wm + i*16 + tr;
            int r1 = r0 + 8;
            #pragma unroll
            for (int j = 0; j < 4; j++){
                int cl = wn + j*8 + tc*2;
                float4 v = acc[i][j];
                v.x += __half2float(sB[cl*104 + r0]);  v.y += __half2float(sB[(cl+1)*104 + r0]);
                v.z += __half2float(sB[cl*104 + r1]);  v.w += __half2float(sB[(cl+1)*104 + r1]);
                *(float2*)&g_x1[(b*D_+r0)*T_ + t0 + cl] = make_float2(v.x, v.y);
                *(float2*)&g_x1[(b*D_+r1)*T_ + t0 + cl] = make_float2(v.z, v.w);
            }
        }
    }
}

// K3: fused BN stats + apply (single read), write half. grid=D_, 512 thr.
__global__ void k_bn(const float* __restrict__ gamma, const float* __restrict__ beta){
    int d = blockIdx.x;
    int tid = threadIdx.x;
    float4 v[4];
    float s = 0.f, ss = 0.f;
    #pragma unroll
    for (int r = 0; r < 4; r++){
        int i = tid + r*512;
        int b = i >> 7, t4 = i & 127;
        v[r] = *(const float4*)&g_x1[(b*D_+d)*T_ + t4*4];
        s  += (v[r].x + v[r].y) + (v[r].z + v[r].w);
        ss += (v[r].x*v[r].x + v[r].y*v[r].y) + (v[r].z*v[r].z + v[r].w*v[r].w);
    }
    s = warp_sum(s); ss = warp_sum(ss);
    __shared__ float r1[16], r2[16];
    __shared__ float bsc, bof;
    int w = tid >> 5;
    if ((tid & 31) == 0){ r1[w] = s; r2[w] = ss; }
    __syncthreads();
    if (tid == 0){
        float S = 0.f, SS = 0.f;
        #pragma unroll
        for (int k = 0; k < 16; k++){ S += r1[k]; SS += r2[k]; }
        const float invN = 1.f/(float)(B_*T_);
        float mean = S * invN;
        float var  = SS * invN - mean*mean;
        float rs = rsqrtf(var + 1e-5f);
        float sc = rs * gamma[d];
        bsc = sc; bof = beta[d] - mean * sc;
    }
    __syncthreads();
    float sc = bsc, of = bof;
    #pragma unroll
    for (int r = 0; r < 4; r++){
        int i = tid + r*512;
        int b = i >> 7, t4 = i & 127;
        float4 q = v[r];
        __half2 h01 = __floats2half2_rn(fmaf(q.x, sc, of), fmaf(q.y, sc, of));
        __half2 h23 = __floats2half2_rn(fmaf(q.z, sc, of), fmaf(q.w, sc, of));
        __half* dst = g_x2r + (b*D_+d)*T_ + t4*4;
        *(__half2*)dst       = h01;
        *(__half2*)(dst + 2) = h23;
    }
}

// ======================= fp16 mma.sync GEMM (ldmatrix + cp.async) =======================
// C = epi( A[M,K] @ Bt[N,K]^T + bias [+ Res] ); A,Bt,Res fp16; acc fp32.
// CTA 128x64, BK=64 halves (128B rows + 16B pad), 8 warps (4m x 2n), 3-stage cp.async.
#define ASTG 18432   // 128*144 bytes
#define BSTG 9216    // 64*144
#define STG  (ASTG + BSTG)
#define GEMM_SMEM (3*STG)   // 82944

template<bool GELU, bool HALF_OUT, bool RESID, bool SPLITK>
__global__ void __launch_bounds__(256, 2) k_mma(
    const __half* __restrict__ A, const __half* __restrict__ Bt,
    const float* __restrict__ bias, const __half* __restrict__ Res,
    void* __restrict__ Cv, int M, int N, int K)
{
    uint32_t sbase = smem_u32(dyn_smem);
    int tid = threadIdx.x, lane = tid & 31, w = tid >> 5;
    int wm = (w & 3) * 32, wn = (w >> 2) * 32;
    int bn = blockIdx.x * 64, bm = blockIdx.y * 128;
    int kz = SPLITK ? blockIdx.z : 0;
    int koff = SPLITK ? kz * (K >> 1) : 0;
    const int KT = (SPLITK ? (K >> 1) : K) / 64;
    bool lead = (!SPLITK) || (kz == 0);

    // A: 128 rows x 8 chunks(16B=8 halves) = 4/thread; B: 64 rows x 8 = 2/thread
    uint32_t aSm[4]; const __half* aG[4];
    #pragma unroll
    for (int r = 0; r < 4; r++){
        int idx = tid + r*256, m = idx >> 3, kc = idx & 7;
        aSm[r] = (uint32_t)(m*144 + kc*16);
        aG[r]  = A + (size_t)(bm + m)*K + koff + kc*8;
    }
    uint32_t bSm[2]; const __half* bG[2];
    #pragma unroll
    for (int r = 0; r < 2; r++){
        int idx = tid + r*256, n = idx >> 3, kc = idx & 7;
        bSm[r] = (uint32_t)(ASTG + n*144 + kc*16);
        bG[r]  = Bt + (size_t)(bn + n)*K + koff + kc*8;
    }

    uint32_t aF[2], bF[2];
    {
        int rlo = lane & 7, rmid = (lane >> 3) & 1, khi = lane >> 4;
        aF[0] = (uint32_t)((wm + rlo + 8*rmid)*144 + 16*khi);
        aF[1] = aF[0] + 16*144;
        bF[0] = (uint32_t)(ASTG + (wn      + khi*8 + rlo)*144 + 16*rmid);
        bF[1] = (uint32_t)(ASTG + (wn + 16 + khi*8 + rlo)*144 + 16*rmid);
    }

    float4 acc[2][4];
    #pragma unroll
    for (int i = 0; i < 2; i++)
        #pragma unroll
        for (int j = 0; j < 4; j++) acc[i][j] = make_float4(0.f,0.f,0.f,0.f);

    #pragma unroll
    for (int s = 0; s < 2; s++){
        uint32_t st = sbase + s*STG;
        #pragma unroll
        for (int r = 0; r < 4; r++) cp16(st + aSm[r], aG[r] + s*64);
        #pragma unroll
        for (int r = 0; r < 2; r++) cp16(st + bSm[r], bG[r] + s*64);
        CP_COMMIT();
    }

    int cur = 0, nxtbuf = 2;
    for (int kt = 0; kt < KT; kt++){
        if (kt < KT-1) CP_WAIT1(); else CP_WAIT0();
        __syncthreads();
        if (kt + 2 < KT){
            uint32_t st = sbase + nxtbuf*STG;
            #pragma unroll
            for (int r = 0; r < 4; r++) cp16(st + aSm[r], aG[r] + (kt+2)*64);
            #pragma unroll
            for (int r = 0; r < 2; r++) cp16(st + bSm[r], bG[r] + (kt+2)*64);
            CP_COMMIT();
        }
        uint32_t st = sbase + cur*STG;
        #pragma unroll
        for (int ks = 0; ks < 4; ks++){        // 4 x k16 = 64
            uint32_t a0[4], a1[4], b0[4], b1[4];
            ldsm_x4(a0, st + aF[0] + ks*32);
            ldsm_x4(a1, st + aF[1] + ks*32);
            ldsm_x4(b0, st + bF[0] + ks*32);
            ldsm_x4(b1, st + bF[1] + ks*32);
            mma_f16(acc[0][0], a0, b0[0], b0[1]);
            mma_f16(acc[0][1], a0, b0[2], b0[3]);
            mma_f16(acc[0][2], a0, b1[0], b1[1]);
            mma_f16(acc[0][3], a0, b1[2], b1[3]);
            mma_f16(acc[1][0], a1, b0[0], b0[1]);
            mma_f16(acc[1][1], a1, b0[2], b0[3]);
            mma_f16(acc[1][2], a1, b1[0], b1[1]);
            mma_f16(acc[1][3], a1, b1[2], b1[3]);
        }
        cur = (cur + 1 == 3) ? 0 : cur + 1;
        nxtbuf = (nxtbuf + 1 == 3) ? 0 : nxtbuf + 1;
    }

    int tr = lane >> 2, tc = lane & 3;
    #pragma unroll
    for (int i = 0; i < 2; i++){
        int r0 = bm + wm + i*16 + tr;
        int r1 = r0 + 8;
        #pragma unroll
        for (int j = 0; j < 4; j++){
            int col = bn + wn + j*8 + tc*2;
            float4 v = acc[i][j];
            if (lead){
                float2 bb = *(const float2*)&bias[col];
                v.x += bb.x; v.y += bb.y; v.z += bb.x; v.w += bb.y;
            }
            if (GELU){
                v.x = 0.5f*v.x*(1.0f + erff(v.x*0.7071067811865476f));
                v.y = 0.5f*v.y*(1.0f + erff(v.y*0.7071067811865476f));
                v.z = 0.5f*v.z*(1.0f + erff(v.z*0.7071067811865476f));
                v.w = 0.5f*v.w*(1.0f + erff(v.w*0.7071067811865476f));
            }
            if (RESID && lead){
                __half2 q0 = *(const __half2*)&Res[(size_t)r0*N + col];
                __half2 q1 = *(const __half2*)&Res[(size_t)r1*N + col];
                float2 f0 = __half22float2(q0), f1 = __half22float2(q1);
                v.x += f0.x; v.y += f0.y; v.z += f1.x; v.w += f1.y;
            }
            if (HALF_OUT){
                __half* Ch = (__half*)Cv;
                *(__half2*)&Ch[(size_t)r0*N + col] = __floats2half2_rn(v.x, v.y);
                *(__half2*)&Ch[(size_t)r1*N + col] = __floats2half2_rn(v.z, v.w);
            } else {
                float* Cf = (float*)Cv + (SPLITK ? (size_t)kz * M * N : 0);
                *(float2*)&Cf[(size_t)r0*N + col] = make_float2(v.x, v.y);
                *(float2*)&Cf[(size_t)r1*N + col] = make_float2(v.z, v.w);
            }
        }
    }
}

// K6: LayerNorm over T (sums the 2 split-K partials), write final output
__global__ void k_ln(const float* __restrict__ lng, const float* __restrict__ lnb,
                     float* __restrict__ out){
    int row = blockIdx.x;
    const float* y0 = g_y + (size_t)row*T_;
    const float* y1 = g_y + (size_t)BD_*T_ + (size_t)row*T_;
    int tid = threadIdx.x;
    float a = y0[tid]       + y1[tid];
    float b = y0[tid + 256] + y1[tid + 256];
    __shared__ float red[8];
    int w = tid >> 5;
    float s = warp_sum(a + b);
    if ((tid & 31) == 0) red[w] = s;
    __syncthreads();
    float S = 0.f;
    #pragma unroll
    for (int k = 0; k < 8; k++) S += red[k];
    float mean = S * (1.f/512.f);
    float d0 = a - mean, d1 = b - mean;
    __syncthreads();
    float ss = warp_sum(d0*d0 + d1*d1);
    if ((tid & 31) == 0) red[w] = ss;
    __syncthreads();
    float SS = 0.f;
    #pragma unroll
    for (int k = 0; k < 8; k++) SS += red[k];
    float rs = rsqrtf(SS * (1.f/512.f) + 1e-5f);
    out[row*T_ + tid]       = d0*rs*lng[tid]       + lnb[tid];
    out[row*T_ + tid + 256] = d1*rs*lng[tid + 256] + lnb[tid + 256];
}

extern "C" void kernel_launch(void* const* d_in, const int* in_sizes, int n_in,
                              void* d_out, int out_size){
    const float* residual = (const float*)d_in[0];
    const float* bn_g = (const float*)d_in[1];
    const float* bn_b = (const float*)d_in[2];
    const float* ln_g = (const float*)d_in[3];
    const float* ln_b = (const float*)d_in[4];
    const float* W1   = (const float*)d_in[5];
    const float* b1   = (const float*)d_in[6];
    const float* W2   = (const float*)d_in[7];
    const float* b2   = (const float*)d_in[8];
    float* out = (float*)d_out;

    cudaFuncSetAttribute(k_attn, cudaFuncAttributeMaxDynamicSharedMemorySize, ATTN_SMEM);
    cudaFuncSetAttribute(k_mma<true,  true,  false, false>, cudaFuncAttributeMaxDynamicSharedMemorySize, GEMM_SMEM);
    cudaFuncSetAttribute(k_mma<false, false, true,  true >, cudaFuncAttributeMaxDynamicSharedMemorySize, GEMM_SMEM);

    __half *px2r, *ph, *pw1t, *pw2t;
    float *py;
    cudaGetSymbolAddress((void**)&px2r, g_x2r);
    cudaGetSymbolAddress((void**)&ph,   g_h);
    cudaGetSymbolAddress((void**)&py,   g_y);
    cudaGetSymbolAddress((void**)&pw1t, g_w1t);
    cudaGetSymbolAddress((void**)&pw2t, g_w2t);

    k_pre<<<1024 + B_, 256>>>(W1, pw1t, W2, pw2t, residual);

    dim3 ga(T_/64, B_);
    k_attn<<<ga, 256, ATTN_SMEM>>>(residual);
    k_bn<<<D_, 512>>>(bn_g, bn_b);

    // GEMM1: h = half( GELU(x2r @ W1 + b1) )   [1536 x 1024 x 512], 192 CTAs
    dim3 g1(H_/64, BD_/128);
    k_mma<true,  true,  false, false><<<g1, 256, GEMM_SMEM>>>(px2r, pw1t, b1, nullptr, ph, BD_, H_, T_);
    // GEMM2: y = h @ W2 + b2 + x2r, split-K x2  [1536 x 512 x 1024], 192 CTAs
    dim3 g2(T_/64, BD_/128, 2);
    k_mma<false, false, true,  true ><<<g2, 256, GEMM_SMEM>>>(ph, pw2t, b2, px2r, py, BD_, T_, H_);

    k_ln<<<BD_, 256>>>(ln_g, ln_b, out);
}

// round 12
// speedup vs baseline: 1.5644x; 1.1472x over previous
#include <cuda_runtime.h>
#include <cuda_fp16.h>
#include <math.h>
#include <stdint.h>

#define B_  16
#define D_  96
#define T_  512
#define H_  1024
#define BD_ (B_*D_)

// ---- scratch ----
__device__ float  g_A[B_*D_*D_];    // softmax corr (fp32)
__device__ float  g_x1[BD_*T_];     // attn+res (fp32, for BN stats)
__device__ __half g_x2r[BD_*T_];    // BN(x1) fp16 (GEMM1 A + GEMM2 residual)
__device__ __half g_h[BD_*H_];      // GELU output fp16
__device__ float  g_y[2*BD_*T_];    // GEMM2 split-K partials (fp32)
__device__ __half g_w1h[T_*H_];     // W1 [T][H] fp16 (natural layout)
__device__ __half g_w2h[H_*T_];     // W2 [H][T] fp16 (natural layout)

extern __shared__ char dyn_smem[];

__device__ __forceinline__ float warp_sum(float v){
    #pragma unroll
    for(int o=16;o>0;o>>=1) v += __shfl_xor_sync(0xffffffffu, v, o);
    return v;
}
__device__ __forceinline__ float warp_max(float v){
    #pragma unroll
    for(int o=16;o>0;o>>=1) v = fmaxf(v, __shfl_xor_sync(0xffffffffu, v, o));
    return v;
}
__device__ __forceinline__ uint32_t smem_u32(const void* p){
    uint32_t a;
    asm("{ .reg .u64 t; cvta.to.shared.u64 t, %1; cvt.u32.u64 %0, t; }" : "=r"(a) : "l"(p));
    return a;
}
__device__ __forceinline__ void mma_f16(float4& d, const uint32_t a[4], uint32_t b0, uint32_t b1){
    asm volatile("mma.sync.aligned.m16n8k16.row.col.f32.f16.f16.f32 "
        "{%0,%1,%2,%3}, {%4,%5,%6,%7}, {%8,%9}, {%0,%1,%2,%3};"
        : "+f"(d.x), "+f"(d.y), "+f"(d.z), "+f"(d.w)
        : "r"(a[0]), "r"(a[1]), "r"(a[2]), "r"(a[3]), "r"(b0), "r"(b1));
}
__device__ __forceinline__ void ldsm_x4(uint32_t* r, uint32_t addr){
    asm volatile("ldmatrix.sync.aligned.m8n8.x4.shared.b16 {%0,%1,%2,%3}, [%4];"
        : "=r"(r[0]), "=r"(r[1]), "=r"(r[2]), "=r"(r[3]) : "r"(addr));
}
__device__ __forceinline__ void ldsm_x4t(uint32_t* r, uint32_t addr){
    asm volatile("ldmatrix.sync.aligned.m8n8.x4.trans.shared.b16 {%0,%1,%2,%3}, [%4];"
        : "=r"(r[0]), "=r"(r[1]), "=r"(r[2]), "=r"(r[3]) : "r"(addr));
}
__device__ __forceinline__ void cp16(uint32_t dst, const void* src){
    asm volatile("cp.async.ca.shared.global [%0], [%1], 16;" :: "r"(dst), "l"(src));
}
#define CP_COMMIT() asm volatile("cp.async.commit_group;" ::: "memory")
#define CP_WAIT1()  asm volatile("cp.async.wait_group 1;" ::: "memory")
#define CP_WAIT0()  asm volatile("cp.async.wait_group 0;" ::: "memory")

// K0: fp32->fp16 weight convert (same layout) + corr softmax.
// blocks [0,128): W1; [128,256): W2; [256,272): corr.
__global__ void k_pre(const float* __restrict__ W1, __half* __restrict__ W1h,
                      const float* __restrict__ W2, __half* __restrict__ W2h,
                      const float* __restrict__ res){
    int bid = blockIdx.x;
    if (bid < 256){
        const float* W = (bid < 128) ? W1 : W2;
        __half* Wh = (bid < 128) ? W1h : W2h;
        int base = (bid & 127) * 4096;                 // floats (1024 float4 per block)
        #pragma unroll
        for (int i = 0; i < 4; i++){
            int idx = base + (threadIdx.x + i*256)*4;
            float4 v = *(const float4*)&W[idx];
            __half2 h01 = __floats2half2_rn(v.x, v.y);
            __half2 h23 = __floats2half2_rn(v.z, v.w);
            *(__half2*)&Wh[idx]     = h01;
            *(__half2*)&Wh[idx + 2] = h23;
        }
        return;
    }
    __shared__ float s[D_];
    int b = bid - 256;
    int w = threadIdx.x >> 5, lane = threadIdx.x & 31;
    for (int r = w; r < D_; r += 8){
        const float4* p = (const float4*)(res + (b*D_ + r)*T_);
        float v = 0.f;
        #pragma unroll
        for (int k = 0; k < 4; k++){
            float4 q = p[lane + k*32];
            v += (q.x + q.y) + (q.z + q.w);
        }
        v = warp_sum(v);
        if (lane == 0) s[r] = v;
    }
    __syncthreads();
    const float SCALE = 1.0f/11585.237502960395f;   // 1/512^1.5
    for (int r = w; r < D_; r += 8){
        float si = s[r];
        float z0 = si * s[lane     ] * SCALE;
        float z1 = si * s[lane + 32] * SCALE;
        float z2 = si * s[lane + 64] * SCALE;
        float m = warp_max(fmaxf(z0, fmaxf(z1, z2)));
        float e0 = expf(z0 - m), e1 = expf(z1 - m), e2 = expf(z2 - m);
        float inv = 1.f / warp_sum(e0 + e1 + e2);
        float* o = g_A + (b*D_ + r)*D_;
        o[lane]      = e0 * inv;
        o[lane + 32] = e1 * inv;
        o[lane + 64] = e2 * inv;
    }
}

// K2: x1 = (I+A) @ X via fp16 mma. grid (T/64, B), 256 thr.
// sA [128 d][104 h] (rows 96+ garbage, discarded); sB [96 e][72 h] = X staged [e][t].
#define AT_SB_BYTES (128*208)          // 26624
#define ATTN_SMEM   (AT_SB_BYTES + 96*144)   // 40448 B
__global__ void __launch_bounds__(256) k_attn(const float* __restrict__ res){
    __half* sA = (__half*)dyn_smem;               // stride 104 halves (208B)
    __half* sB = (__half*)(dyn_smem + AT_SB_BYTES); // stride 72 halves (144B)
    uint32_t sbase = smem_u32(dyn_smem);
    int b  = blockIdx.y;
    int t0 = blockIdx.x * 64;
    int tid = threadIdx.x, lane = tid & 31, w = tid >> 5;

    // stage A [96x96] fp32 -> half, [d][e]
    for (int i = tid; i < D_*D_/4; i += 256){
        int d = (i*4)/D_, e = (i*4)%D_;
        float4 v = *(const float4*)&g_A[(b*D_+d)*D_ + e];
        *(__half2*)&sA[d*104 + e]     = __floats2half2_rn(v.x, v.y);
        *(__half2*)&sA[d*104 + e + 2] = __floats2half2_rn(v.z, v.w);
    }
    // stage X [96 e][64 t] coalesced float4 -> half
    for (int i = tid; i < D_*16; i += 256){
        int e = i >> 4, t4 = (i & 15)*4;
        float4 v = *(const float4*)&res[(b*D_+e)*T_ + t0 + t4];
        *(__half2*)&sB[e*72 + t4]     = __floats2half2_rn(v.x, v.y);
        *(__half2*)&sB[e*72 + t4 + 2] = __floats2half2_rn(v.z, v.w);
    }
    __syncthreads();

    int wm = (w & 3) * 32, wn = (w >> 2) * 32;
    uint32_t aF0, aF1, bF0, bF1;
    {
        int rlo = lane & 7, mid = (lane >> 3) & 1, hi = lane >> 4;
        aF0 = sbase + (uint32_t)((wm + rlo + 8*mid)*208 + 16*hi);
        aF1 = aF0 + 16*208;
        // B trans: rows = k(e), cols = n(t)
        bF0 = sbase + (uint32_t)(AT_SB_BYTES + (mid*8 + rlo)*144 + (wn + hi*8)*2);
        bF1 = bF0 + 32;   // +16 t-cols
    }
    float4 acc[2][4];
    #pragma unroll
    for (int i = 0; i < 2; i++)
        #pragma unroll
        for (int j = 0; j < 4; j++) acc[i][j] = make_float4(0.f,0.f,0.f,0.f);

    #pragma unroll
    for (int ks = 0; ks < 6; ks++){            // 6 x k16 = 96
        uint32_t a0[4], a1[4], b0[4], b1[4];
        ldsm_x4 (a0, aF0 + ks*32);
        ldsm_x4 (a1, aF1 + ks*32);
        ldsm_x4t(b0, bF0 + ks*2304);           // 16 rows * 144B
        ldsm_x4t(b1, bF1 + ks*2304);
        mma_f16(acc[0][0], a0, b0[0], b0[1]);
        mma_f16(acc[0][1], a0, b0[2], b0[3]);
        mma_f16(acc[0][2], a0, b1[0], b1[1]);
        mma_f16(acc[0][3], a0, b1[2], b1[3]);
        mma_f16(acc[1][0], a1, b0[0], b0[1]);
        mma_f16(acc[1][1], a1, b0[2], b0[3]);
        mma_f16(acc[1][2], a1, b1[0], b1[1]);
        mma_f16(acc[1][3], a1, b1[2], b1[3]);
    }

    if (wm < 96){
        int tr = lane >> 2, tc = lane & 3;
        #pragma unroll
        for (int i = 0; i < 2; i++){
            int r0 = wm + i*16 + tr;
            int r1 = r0 + 8;
            #pragma unroll
            for (int j = 0; j < 4; j++){
                int cl = wn + j*8 + tc*2;
                float4 v = acc[i][j];
                v.x += __half2float(sB[r0*72 + cl]);   v.y += __half2float(sB[r0*72 + cl+1]);
                v.z += __half2float(sB[r1*72 + cl]);   v.w += __half2float(sB[r1*72 + cl+1]);
                *(float2*)&g_x1[(b*D_+r0)*T_ + t0 + cl] = make_float2(v.x, v.y);
                *(float2*)&g_x1[(b*D_+r1)*T_ + t0 + cl] = make_float2(v.z, v.w);
            }
        }
    }
}

// K3: fused BN stats + apply (single read), write half. grid=D_, 512 thr.
__global__ void k_bn(const float* __restrict__ gamma, const float* __restrict__ beta){
    int d = blockIdx.x;
    int tid = threadIdx.x;
    float4 v[4];
    float s = 0.f, ss = 0.f;
    #pragma unroll
    for (int r = 0; r < 4; r++){
        int i = tid + r*512;
        int b = i >> 7, t4 = i & 127;
        v[r] = *(const float4*)&g_x1[(b*D_+d)*T_ + t4*4];
        s  += (v[r].x + v[r].y) + (v[r].z + v[r].w);
        ss += (v[r].x*v[r].x + v[r].y*v[r].y) + (v[r].z*v[r].z + v[r].w*v[r].w);
    }
    s = warp_sum(s); ss = warp_sum(ss);
    __shared__ float r1[16], r2[16];
    __shared__ float bsc, bof;
    int w = tid >> 5;
    if ((tid & 31) == 0){ r1[w] = s; r2[w] = ss; }
    __syncthreads();
    if (tid == 0){
        float S = 0.f, SS = 0.f;
        #pragma unroll
        for (int k = 0; k < 16; k++){ S += r1[k]; SS += r2[k]; }
        const float invN = 1.f/(float)(B_*T_);
        float mean = S * invN;
        float var  = SS * invN - mean*mean;
        float rs = rsqrtf(var + 1e-5f);
        float sc = rs * gamma[d];
        bsc = sc; bof = beta[d] - mean * sc;
    }
    __syncthreads();
    float sc = bsc, of = bof;
    #pragma unroll
    for (int r = 0; r < 4; r++){
        int i = tid + r*512;
        int b = i >> 7, t4 = i & 127;
        float4 q = v[r];
        __half* dst = g_x2r + (b*D_+d)*T_ + t4*4;
        *(__half2*)dst       = __floats2half2_rn(fmaf(q.x, sc, of), fmaf(q.y, sc, of));
        *(__half2*)(dst + 2) = __floats2half2_rn(fmaf(q.z, sc, of), fmaf(q.w, sc, of));
    }
}

// ======================= fp16 mma.sync GEMM, 64x64 tiles =======================
// C = epi( A[M,K] @ W[K,N] + bias [+ Res] ); A,W,Res fp16; acc fp32.
// W in NATURAL [K][N] layout; B fragments via ldmatrix.trans.
// CTA 64x64, BK=64 halves, 128 thr (4 warps 2m x 2n), 3-stage cp.async.
#define ASTG 9216    // 64*144
#define BSTG 9216
#define STG  (ASTG + BSTG)
#define GEMM_SMEM (3*STG)   // 55296

template<bool GELU, bool HALF_OUT, bool RESID, bool SPLITK>
__global__ void __launch_bounds__(128) k_mma(
    const __half* __restrict__ A, const __half* __restrict__ Bw,
    const float* __restrict__ bias, const __half* __restrict__ Res,
    void* __restrict__ Cv, int M, int N, int K)
{
    uint32_t sbase = smem_u32(dyn_smem);
    int tid = threadIdx.x, lane = tid & 31, w = tid >> 5;
    int wm = (w & 1) * 32, wn = (w >> 1) * 32;
    int bn = blockIdx.x * 64, bm = blockIdx.y * 64;
    int kz = SPLITK ? blockIdx.z : 0;
    int koff = SPLITK ? kz * (K >> 1) : 0;
    const int KT = (SPLITK ? (K >> 1) : K) / 64;
    bool lead = (!SPLITK) || (kz == 0);

    // A: 64 m-rows x 8 chunks; B: 64 k-rows x 8 chunks; 4 each per thread
    uint32_t aSm[4]; const __half* aG[4];
    uint32_t bSm[4]; const __half* bG[4];
    #pragma unroll
    for (int r = 0; r < 4; r++){
        int idx = tid + r*128, row = idx >> 3, c = idx & 7;
        aSm[r] = (uint32_t)(row*144 + c*16);
        aG[r]  = A + (size_t)(bm + row)*K + koff + c*8;
        bSm[r] = (uint32_t)(ASTG + row*144 + c*16);
        bG[r]  = Bw + (size_t)(koff + row)*N + bn + c*8;
    }

    uint32_t aF[2], bF[2];
    {
        int rlo = lane & 7, mid = (lane >> 3) & 1, hi = lane >> 4;
        aF[0] = (uint32_t)((wm + rlo + 8*mid)*144 + 16*hi);
        aF[1] = aF[0] + 16*144;
        bF[0] = (uint32_t)(ASTG + (mid*8 + rlo)*144 + (wn + hi*8)*2);
        bF[1] = bF[0] + 32;   // +16 n-cols
    }

    float4 acc[2][4];
    #pragma unroll
    for (int i = 0; i < 2; i++)
        #pragma unroll
        for (int j = 0; j < 4; j++) acc[i][j] = make_float4(0.f,0.f,0.f,0.f);

    #pragma unroll
    for (int s = 0; s < 2; s++){
        uint32_t st = sbase + s*STG;
        #pragma unroll
        for (int r = 0; r < 4; r++){
            cp16(st + aSm[r], aG[r] + (size_t)s*64);
            cp16(st + bSm[r], bG[r] + (size_t)s*64*N);
        }
        CP_COMMIT();
    }

    int cur = 0, nxtbuf = 2;
    for (int kt = 0; kt < KT; kt++){
        if (kt < KT-1) CP_WAIT1(); else CP_WAIT0();
        __syncthreads();
        if (kt + 2 < KT){
            uint32_t st = sbase + nxtbuf*STG;
            #pragma unroll
            for (int r = 0; r < 4; r++){
                cp16(st + aSm[r], aG[r] + (size_t)(kt+2)*64);
                cp16(st + bSm[r], bG[r] + (size_t)(kt+2)*64*N);
            }
            CP_COMMIT();
        }
        uint32_t st = sbase + cur*STG;
        #pragma unroll
        for (int ks = 0; ks < 4; ks++){        // 4 x k16 = 64
            uint32_t a0[4], a1[4], b0[4], b1[4];
            ldsm_x4 (a0, st + aF[0] + ks*32);
            ldsm_x4 (a1, st + aF[1] + ks*32);
            ldsm_x4t(b0, st + bF[0] + ks*2304);
            ldsm_x4t(b1, st + bF[1] + ks*2304);
            mma_f16(acc[0][0], a0, b0[0], b0[1]);
            mma_f16(acc[0][1], a0, b0[2], b0[3]);
            mma_f16(acc[0][2], a0, b1[0], b1[1]);
            mma_f16(acc[0][3], a0, b1[2], b1[3]);
            mma_f16(acc[1][0], a1, b0[0], b0[1]);
            mma_f16(acc[1][1], a1, b0[2], b0[3]);
            mma_f16(acc[1][2], a1, b1[0], b1[1]);
            mma_f16(acc[1][3], a1, b1[2], b1[3]);
        }
        cur = (cur + 1 == 3) ? 0 : cur + 1;
        nxtbuf = (nxtbuf + 1 == 3) ? 0 : nxtbuf + 1;
    }

    int tr = lane >> 2, tc = lane & 3;
    #pragma unroll
    for (int i = 0; i < 2; i++){
        int r0 = bm + wm + i*16 + tr;
        int r1 = r0 + 8;
        #pragma unroll
        for (int j = 0; j < 4; j++){
            int col = bn + wn + j*8 + tc*2;
            float4 v = acc[i][j];
            if (lead){
                float2 bb = *(const float2*)&bias[col];
                v.x += bb.x; v.y += bb.y; v.z += bb.x; v.w += bb.y;
            }
            if (GELU){
                v.x = 0.5f*v.x*(1.0f + erff(v.x*0.7071067811865476f));
                v.y = 0.5f*v.y*(1.0f + erff(v.y*0.7071067811865476f));
                v.z = 0.5f*v.z*(1.0f + erff(v.z*0.7071067811865476f));
                v.w = 0.5f*v.w*(1.0f + erff(v.w*0.7071067811865476f));
            }
            if (RESID && lead){
                float2 f0 = __half22float2(*(const __half2*)&Res[(size_t)r0*N + col]);
                float2 f1 = __half22float2(*(const __half2*)&Res[(size_t)r1*N + col]);
                v.x += f0.x; v.y += f0.y; v.z += f1.x; v.w += f1.y;
            }
            if (HALF_OUT){
                __half* Ch = (__half*)Cv;
                *(__half2*)&Ch[(size_t)r0*N + col] = __floats2half2_rn(v.x, v.y);
                *(__half2*)&Ch[(size_t)r1*N + col] = __floats2half2_rn(v.z, v.w);
            } else {
                float* Cf = (float*)Cv + (SPLITK ? (size_t)kz * M * N : 0);
                *(float2*)&Cf[(size_t)r0*N + col] = make_float2(v.x, v.y);
                *(float2*)&Cf[(size_t)r1*N + col] = make_float2(v.z, v.w);
            }
        }
    }
}

// K6: LayerNorm over T (sums the 2 split-K partials), write final output
__global__ void k_ln(const float* __restrict__ lng, const float* __restrict__ lnb,
                     float* __restrict__ out){
    int row = blockIdx.x;
    const float* y0 = g_y + (size_t)row*T_;
    const float* y1 = g_y + (size_t)BD_*T_ + (size_t)row*T_;
    int tid = threadIdx.x;
    float a = y0[tid]       + y1[tid];
    float b = y0[tid + 256] + y1[tid + 256];
    __shared__ float red[8];
    int w = tid >> 5;
    float s = warp_sum(a + b);
    if ((tid & 31) == 0) red[w] = s;
    __syncthreads();
    float S = 0.f;
    #pragma unroll
    for (int k = 0; k < 8; k++) S += red[k];
    float mean = S * (1.f/512.f);
    float d0 = a - mean, d1 = b - mean;
    __syncthreads();
    float ss = warp_sum(d0*d0 + d1*d1);
    if ((tid & 31) == 0) red[w] = ss;
    __syncthreads();
    float SS = 0.f;
    #pragma unroll
    for (int k = 0; k < 8; k++) SS += red[k];
    float rs = rsqrtf(SS * (1.f/512.f) + 1e-5f);
    out[row*T_ + tid]       = d0*rs*lng[tid]       + lnb[tid];
    out[row*T_ + tid + 256] = d1*rs*lng[tid + 256] + lnb[tid + 256];
}

extern "C" void kernel_launch(void* const* d_in, const int* in_sizes, int n_in,
                              void* d_out, int out_size){
    const float* residual = (const float*)d_in[0];
    const float* bn_g = (const float*)d_in[1];
    const float* bn_b = (const float*)d_in[2];
    const float* ln_g = (const float*)d_in[3];
    const float* ln_b = (const float*)d_in[4];
    const float* W1   = (const float*)d_in[5];
    const float* b1   = (const float*)d_in[6];
    const float* W2   = (const float*)d_in[7];
    const float* b2   = (const float*)d_in[8];
    float* out = (float*)d_out;

    cudaFuncSetAttribute(k_attn, cudaFuncAttributeMaxDynamicSharedMemorySize, ATTN_SMEM);
    cudaFuncSetAttribute(k_mma<true,  true,  false, false>, cudaFuncAttributeMaxDynamicSharedMemorySize, GEMM_SMEM);
    cudaFuncSetAttribute(k_mma<false, false, true,  true >, cudaFuncAttributeMaxDynamicSharedMemorySize, GEMM_SMEM);

    __half *px2r, *ph, *pw1h, *pw2h;
    float *py;
    cudaGetSymbolAddress((void**)&px2r, g_x2r);
    cudaGetSymbolAddress((void**)&ph,   g_h);
    cudaGetSymbolAddress((void**)&py,   g_y);
    cudaGetSymbolAddress((void**)&pw1h, g_w1h);
    cudaGetSymbolAddress((void**)&pw2h, g_w2h);

    k_pre<<<256 + B_, 256>>>(W1, pw1h, W2, pw2h, residual);

    dim3 ga(T_/64, B_);
    k_attn<<<ga, 256, ATTN_SMEM>>>(residual);
    k_bn<<<D_, 512>>>(bn_g, bn_b);

    // GEMM1: h = half( GELU(x2r @ W1 + b1) )   [1536 x 1024 x 512], 384 CTAs
    dim3 g1(H_/64, BD_/64);
    k_mma<true,  true,  false, false><<<g1, 128, GEMM_SMEM>>>(px2r, pw1h, b1, nullptr, ph, BD_, H_, T_);
    // GEMM2: y = h @ W2 + b2 + x2r, split-K x2  [1536 x 512 x 1024], 384 CTAs
    dim3 g2(T_/64, BD_/64, 2);
    k_mma<false, false, true,  true ><<<g2, 128, GEMM_SMEM>>>(ph, pw2h, b2, px2r, py, BD_, T_, H_);

    k_ln<<<BD_, 256>>>(ln_g, ln_b, out);
}